// round 7
// baseline (speedup 1.0000x reference)
#include <cuda_runtime.h>
#include <cuda_bf16.h>

#define B_    16
#define C0    8
#define T0_   32768
#define C1    64
#define T1_   16384
#define C2    128
#define T2_   8192
#define D_    64
#define T3_   4096
#define NC    512

typedef unsigned long long ull;

__device__ __forceinline__ ull pk(float lo, float hi) {
    ull r; asm("mov.b64 %0, {%1, %2};" : "=l"(r) : "f"(lo), "f"(hi)); return r;
}
__device__ __forceinline__ void upk(ull v, float& lo, float& hi) {
    asm("mov.b64 {%0, %1}, %2;" : "=f"(lo), "=f"(hi) : "l"(v));
}
__device__ __forceinline__ ull ffma2(ull a, ull b, ull c) {
    ull d; asm("fma.rn.f32x2 %0, %1, %2, %3;" : "=l"(d) : "l"(a), "l"(b), "l"(c)); return d;
}

__device__ float g_z1[B_ * C1 * T1_];
__device__ float g_z2[B_ * C2 * T2_];
__device__ float g_ze[B_ * D_ * T3_];
__device__ float g_zq[B_ * D_ * T3_];
__device__ float g_r1[B_ * C2 * T2_];
__device__ float g_r2[B_ * C1 * T1_];
__device__ int    g_hist[B_ * NC];
__device__ double g_vq_sse;
__device__ double g_rec_sse;

// encoder: oc-pair weights {wA,wB} (NOT duplicated)
__device__ __align__(16) ull g_w1p[8 * 32 * 8];    // [ic][ocp][slot], tap k<7
__device__ __align__(16) ull g_w2p[64 * 64 * 6];   // [ic][ocp(64)][slot], tap k<5
__device__ __align__(16) ull g_w3p[128 * 32 * 4];  // [ic][ocp][slot], tap k<3
// decoder: duplicated-pair weights (L1-resident LDG path, unchanged)
__device__ __align__(16) ull g_d1d[64 * 128 * 2];
__device__ __align__(16) ull g_d2d[128 * 64 * 2];
__device__ __align__(16) ull g_d3d[64 * 8 * 2];

__global__ void k_init() {
    int i = blockIdx.x * blockDim.x + threadIdx.x;
    if (i < B_ * NC) g_hist[i] = 0;
    if (i == 0) { g_vq_sse = 0.0; g_rec_sse = 0.0; }
}

__global__ void k_prep(const float* __restrict__ w1, const float* __restrict__ w2,
                       const float* __restrict__ w3, const float* __restrict__ dw1,
                       const float* __restrict__ dw2, const float* __restrict__ dw3) {
    int tid = blockIdx.x * blockDim.x + threadIdx.x;
    int NT = gridDim.x * blockDim.x;
    // conv1 pairs: [ic<8][ocp<32][k<7]
    for (int i = tid; i < 8 * 32 * 7; i += NT) {
        int ic = i / 224, r = i - ic * 224, ocp = r / 7, k = r - ocp * 7;
        g_w1p[(ic * 32 + ocp) * 8 + k] =
            pk(w1[(2 * ocp) * 56 + ic * 7 + k], w1[(2 * ocp + 1) * 56 + ic * 7 + k]);
    }
    for (int i = tid; i < 8 * 32; i += NT) g_w1p[i * 8 + 7] = 0ull;
    // conv2 pairs: [ic<64][ocp<64][k<5]
    for (int i = tid; i < 64 * 64 * 5; i += NT) {
        int ic = i / 320, r = i - ic * 320, ocp = r / 5, k = r - ocp * 5;
        g_w2p[(ic * 64 + ocp) * 6 + k] =
            pk(w2[(2 * ocp) * 320 + ic * 5 + k], w2[(2 * ocp + 1) * 320 + ic * 5 + k]);
    }
    for (int i = tid; i < 64 * 64; i += NT) g_w2p[i * 6 + 5] = 0ull;
    // conv3 pairs: [ic<128][ocp<32][k<3]
    for (int i = tid; i < 128 * 32 * 3; i += NT) {
        int ic = i / 96, r = i - ic * 96, ocp = r / 3, k = r - ocp * 3;
        g_w3p[(ic * 32 + ocp) * 4 + k] =
            pk(w3[(2 * ocp) * 384 + ic * 3 + k], w3[(2 * ocp + 1) * 384 + ic * 3 + k]);
    }
    for (int i = tid; i < 128 * 32; i += NT) g_w3p[i * 4 + 3] = 0ull;
    // decoder duplicated pairs
    for (int i = tid; i < 64 * 128; i += NT) {
        float4 v = *(const float4*)(dw1 + i * 4);
        g_d1d[i * 2] = pk(v.w, v.z); g_d1d[i * 2 + 1] = pk(v.y, v.x);
    }
    for (int i = tid; i < 128 * 64; i += NT) {
        float4 v = *(const float4*)(dw2 + i * 4);
        g_d2d[i * 2] = pk(v.w, v.z); g_d2d[i * 2 + 1] = pk(v.y, v.x);
    }
    for (int i = tid; i < 64 * 8; i += NT) {
        float4 v = *(const float4*)(dw3 + i * 4);
        g_d3d[i * 2] = pk(v.w, v.z); g_d3d[i * 2 + 1] = pk(v.y, v.x);
    }
}

// ============================================================================
// conv1: k=7 s=2 p=3 relu. e[j]=X[2(t0+j)-2], o[j]=X[2(t0+j)-3]
// out[v] = o[v]w0+e[v]w1+o[v+1]w2+e[v+1]w3+o[v+2]w4+e[v+2]w5+o[v+3]w6
// oc-pair acc2; inputs duplicated {x,x} in smem
// ============================================================================
__global__ __launch_bounds__(256) void k_conv1(const float* __restrict__ x,
                                               const float* __restrict__ b1) {
    __shared__ __align__(16) ull see[8 * 132], soo[8 * 132];
    __shared__ __align__(16) ull ws[8 * 32 * 8];
    int b = blockIdx.y, t0 = blockIdx.x * 128;
    const float* xr = x + b * C0 * T0_;
    {
        const ulonglong2* src = (const ulonglong2*)g_w1p;
        ulonglong2* dst = (ulonglong2*)ws;
        for (int i = threadIdx.x; i < 1024; i += 256) dst[i] = src[i];
    }
    for (int idx = threadIdx.x; idx < 8 * 132; idx += 256) {
        int ic = idx / 132, j = idx - ic * 132;
        int f = 2 * (t0 + j) - 4;
        float a  = (f >= 0 && f < T0_) ? xr[ic * T0_ + f] : 0.f;
        float bb = (f + 1 >= 0 && f + 1 < T0_) ? xr[ic * T0_ + f + 1] : 0.f;
        if (j >= 1) see[ic * 132 + j - 1] = pk(a, a);
        soo[ic * 132 + j] = pk(bb, bb);
    }
    __syncthreads();
    int lane = threadIdx.x & 31, w = threadIdx.x >> 5;
    int L = lane * 4, p0 = w * 4;
    ull acc[4][4];
    #pragma unroll
    for (int p = 0; p < 4; p++) {
        ull pb_ = pk(b1[w * 8 + 2 * p], b1[w * 8 + 2 * p + 1]);
        #pragma unroll
        for (int v = 0; v < 4; v++) acc[p][v] = pb_;
    }
    #pragma unroll 1
    for (int ic = 0; ic < 8; ic++) {
        const ulonglong2* E = (const ulonglong2*)&see[ic * 132 + L];
        const ulonglong2* O = (const ulonglong2*)&soo[ic * 132 + L];
        ulonglong2 e01 = E[0], e23 = E[1], e45 = E[2];
        ulonglong2 o01 = O[0], o23 = O[1], o45 = O[2], o6x = O[3];
        ull e[6] = {e01.x, e01.y, e23.x, e23.y, e45.x, e45.y};
        ull o[7] = {o01.x, o01.y, o23.x, o23.y, o45.x, o45.y, o6x.x};
        const ulonglong2* Wp = (const ulonglong2*)&ws[(ic * 32 + p0) * 8];
        #pragma unroll
        for (int p = 0; p < 4; p++) {
            ulonglong2 W01 = Wp[p * 4], W23 = Wp[p * 4 + 1];
            ulonglong2 W45 = Wp[p * 4 + 2], W6 = Wp[p * 4 + 3];
            #pragma unroll
            for (int v = 0; v < 4; v++) {
                ull a = acc[p][v];
                a = ffma2(o[v],     W01.x, a); a = ffma2(e[v],     W01.y, a);
                a = ffma2(o[v + 1], W23.x, a); a = ffma2(e[v + 1], W23.y, a);
                a = ffma2(o[v + 2], W45.x, a); a = ffma2(e[v + 2], W45.y, a);
                a = ffma2(o[v + 3], W6.x,  a);
                acc[p][v] = a;
            }
        }
    }
    #pragma unroll
    for (int p = 0; p < 4; p++) {
        float a0, b0, a1, b1v, a2, b2, a3, b3;
        upk(acc[p][0], a0, b0); upk(acc[p][1], a1, b1v);
        upk(acc[p][2], a2, b2); upk(acc[p][3], a3, b3);
        int ocA = w * 8 + 2 * p;
        float4 sA = {fmaxf(a0,0.f), fmaxf(a1,0.f), fmaxf(a2,0.f), fmaxf(a3,0.f)};
        float4 sB = {fmaxf(b0,0.f), fmaxf(b1v,0.f), fmaxf(b2,0.f), fmaxf(b3,0.f)};
        *(float4*)(g_z1 + (b * C1 + ocA) * T1_ + t0 + L) = sA;
        *(float4*)(g_z1 + (b * C1 + ocA + 1) * T1_ + t0 + L) = sB;
    }
}

// ============================================================================
// conv2: k=5 s=2 p=2 relu. e[j]=X[2(t0+j)-2], o[j]=X[2(t0+j)-1]
// out[v] = e[v]w0 + o[v]w1 + e[v+1]w2 + o[v+1]w3 + e[v+2]w4
// 8 chunks of 8 ics; z-split ocs
// ============================================================================
__global__ __launch_bounds__(256) void k_conv2(const float* __restrict__ b2) {
    __shared__ __align__(16) ull see[8 * 132], soo[8 * 132];
    __shared__ __align__(16) ull ws[8 * 32 * 6];
    int b = blockIdx.y, t0 = blockIdx.x * 128, zz = blockIdx.z;
    const float* xin = g_z1 + b * C1 * T1_;
    int lane = threadIdx.x & 31, w = threadIdx.x >> 5;
    int L = lane * 4, p0 = w * 4;
    ull acc[4][4];
    #pragma unroll
    for (int p = 0; p < 4; p++) {
        int ocA = zz * 64 + w * 8 + 2 * p;
        ull pb_ = pk(b2[ocA], b2[ocA + 1]);
        #pragma unroll
        for (int v = 0; v < 4; v++) acc[p][v] = pb_;
    }
    #pragma unroll 1
    for (int ch = 0; ch < 8; ch++) {
        __syncthreads();
        {
            ulonglong2* dst = (ulonglong2*)ws;
            for (int i = threadIdx.x; i < 8 * 96; i += 256) {
                int icl = i / 96, j = i - icl * 96;
                dst[icl * 96 + j] = ((const ulonglong2*)g_w2p)
                    [(((ch * 8 + icl) * 64 + zz * 32) * 6) / 2 + j];
            }
        }
        for (int idx = threadIdx.x; idx < 8 * 131; idx += 256) {
            int ic = idx / 131, j = idx - ic * 131;
            int icg = ch * 8 + ic;
            int f = 2 * (t0 + j) - 2;
            float a, bb;
            if (f >= 0 && f + 1 < T1_) { float2 v = *(const float2*)(xin + icg * T1_ + f); a = v.x; bb = v.y; }
            else { a = (f >= 0 && f < T1_) ? xin[icg * T1_ + f] : 0.f;
                   bb = (f + 1 >= 0 && f + 1 < T1_) ? xin[icg * T1_ + f + 1] : 0.f; }
            see[ic * 132 + j] = pk(a, a);
            soo[ic * 132 + j] = pk(bb, bb);
        }
        __syncthreads();
        #pragma unroll 1
        for (int ic = 0; ic < 8; ic++) {
            const ulonglong2* E = (const ulonglong2*)&see[ic * 132 + L];
            const ulonglong2* O = (const ulonglong2*)&soo[ic * 132 + L];
            ulonglong2 e01 = E[0], e23 = E[1], e45 = E[2];
            ulonglong2 o01 = O[0], o23 = O[1], o4x = O[2];
            ull e[6] = {e01.x, e01.y, e23.x, e23.y, e45.x, e45.y};
            ull o[5] = {o01.x, o01.y, o23.x, o23.y, o4x.x};
            const ulonglong2* Wp = (const ulonglong2*)&ws[(ic * 32 + p0) * 6];
            #pragma unroll
            for (int p = 0; p < 4; p++) {
                ulonglong2 W01 = Wp[p * 3], W23 = Wp[p * 3 + 1], W4 = Wp[p * 3 + 2];
                #pragma unroll
                for (int v = 0; v < 4; v++) {
                    ull a = acc[p][v];
                    a = ffma2(e[v],     W01.x, a); a = ffma2(o[v],     W01.y, a);
                    a = ffma2(e[v + 1], W23.x, a); a = ffma2(o[v + 1], W23.y, a);
                    a = ffma2(e[v + 2], W4.x,  a);
                    acc[p][v] = a;
                }
            }
        }
    }
    #pragma unroll
    for (int p = 0; p < 4; p++) {
        float a0, b0, a1, b1v, a2, b2, a3, b3;
        upk(acc[p][0], a0, b0); upk(acc[p][1], a1, b1v);
        upk(acc[p][2], a2, b2); upk(acc[p][3], a3, b3);
        int ocA = zz * 64 + w * 8 + 2 * p;
        float4 sA = {fmaxf(a0,0.f), fmaxf(a1,0.f), fmaxf(a2,0.f), fmaxf(a3,0.f)};
        float4 sB = {fmaxf(b0,0.f), fmaxf(b1v,0.f), fmaxf(b2,0.f), fmaxf(b3,0.f)};
        *(float4*)(g_z2 + (b * C2 + ocA) * T2_ + t0 + L) = sA;
        *(float4*)(g_z2 + (b * C2 + ocA + 1) * T2_ + t0 + L) = sB;
    }
}

// ============================================================================
// conv3: k=3 s=2 p=1. e[j]=X[2(t0+j)], o[j]=X[2(t0+j)-1]
// out[v] = o[v]w0 + e[v]w1 + o[v+1]w2.  16 chunks of 8 ics
// ============================================================================
__global__ __launch_bounds__(256) void k_conv3(const float* __restrict__ b3) {
    __shared__ __align__(16) ull see[8 * 132], soo[8 * 132];
    __shared__ __align__(16) ull ws[8 * 32 * 4];
    int b = blockIdx.y, t0 = blockIdx.x * 128;
    const float* xin = g_z2 + b * C2 * T2_;
    int lane = threadIdx.x & 31, w = threadIdx.x >> 5;
    int L = lane * 4, p0 = w * 4;
    ull acc[4][4];
    #pragma unroll
    for (int p = 0; p < 4; p++) {
        int ocA = w * 8 + 2 * p;
        ull pb_ = pk(b3[ocA], b3[ocA + 1]);
        #pragma unroll
        for (int v = 0; v < 4; v++) acc[p][v] = pb_;
    }
    #pragma unroll 1
    for (int ch = 0; ch < 16; ch++) {
        __syncthreads();
        {
            ulonglong2* dst = (ulonglong2*)ws;
            for (int i = threadIdx.x; i < 512; i += 256)
                dst[i] = ((const ulonglong2*)g_w3p)[(ch * 8 * 32 * 4) / 2 + i];
        }
        for (int idx = threadIdx.x; idx < 8 * 130; idx += 256) {
            int ic = idx / 130, j = idx - ic * 130;
            int icg = ch * 8 + ic;
            int f = 2 * (t0 + j) - 2;
            float a, bb;
            if (f >= 0 && f + 1 < T2_) { float2 v = *(const float2*)(xin + icg * T2_ + f); a = v.x; bb = v.y; }
            else { a = (f >= 0 && f < T2_) ? xin[icg * T2_ + f] : 0.f;
                   bb = (f + 1 >= 0 && f + 1 < T2_) ? xin[icg * T2_ + f + 1] : 0.f; }
            if (j >= 1) see[ic * 132 + j - 1] = pk(a, a);
            soo[ic * 132 + j] = pk(bb, bb);
        }
        __syncthreads();
        #pragma unroll 1
        for (int ic = 0; ic < 8; ic++) {
            const ulonglong2* E = (const ulonglong2*)&see[ic * 132 + L];
            const ulonglong2* O = (const ulonglong2*)&soo[ic * 132 + L];
            ulonglong2 e01 = E[0], e23 = E[1];
            ulonglong2 o01 = O[0], o23 = O[1], o4x = O[2];
            ull e[4] = {e01.x, e01.y, e23.x, e23.y};
            ull o[5] = {o01.x, o01.y, o23.x, o23.y, o4x.x};
            const ulonglong2* Wp = (const ulonglong2*)&ws[(ic * 32 + p0) * 4];
            #pragma unroll
            for (int p = 0; p < 4; p++) {
                ulonglong2 W01 = Wp[p * 2], W2 = Wp[p * 2 + 1];
                #pragma unroll
                for (int v = 0; v < 4; v++) {
                    ull a = acc[p][v];
                    a = ffma2(o[v],     W01.x, a);
                    a = ffma2(e[v],     W01.y, a);
                    a = ffma2(o[v + 1], W2.x,  a);
                    acc[p][v] = a;
                }
            }
        }
    }
    #pragma unroll
    for (int p = 0; p < 4; p++) {
        float a0, b0, a1, b1v, a2, b2, a3, b3;
        upk(acc[p][0], a0, b0); upk(acc[p][1], a1, b1v);
        upk(acc[p][2], a2, b2); upk(acc[p][3], a3, b3);
        int ocA = w * 8 + 2 * p;
        float4 sA = {a0, a1, a2, a3};
        float4 sB = {b0, b1v, b2, b3};
        *(float4*)(g_ze + (b * D_ + ocA) * T3_ + t0 + L) = sA;
        *(float4*)(g_ze + (b * D_ + ocA + 1) * T3_ + t0 + L) = sB;
    }
}

__global__ __launch_bounds__(256) void k_quant(const float* __restrict__ cb) {
    __shared__ __align__(16) float scb[128 * 64];
    __shared__ float snorm[128];
    __shared__ int   shist[NC];
    __shared__ float sred[8];
    int tid = threadIdx.x;
    int g = blockIdx.x * 256 + tid;
    int b = g >> 12, t = g & 4095;
    for (int i = tid; i < NC; i += 256) shist[i] = 0;
    float z[64];
    const float* zp = g_ze + b * D_ * T3_ + t;
    #pragma unroll
    for (int d = 0; d < 64; d++) z[d] = zp[d * T3_];
    float zz = 0.f;
    #pragma unroll
    for (int d = 0; d < 64; d++) zz += z[d] * z[d];
    ull z2[32];
    #pragma unroll
    for (int q = 0; q < 32; q++) z2[q] = pk(z[2 * q], z[2 * q + 1]);
    float best = 3.4e38f;
    int bi = 0;
    for (int ch = 0; ch < 4; ch++) {
        __syncthreads();
        for (int i = tid; i < 128 * 64; i += 256) scb[i] = cb[ch * 8192 + i];
        __syncthreads();
        for (int c = tid; c < 128; c += 256) {
            float n = 0.f;
            for (int d = 0; d < 64; d++) { float v = scb[c * 64 + d]; n += v * v; }
            snorm[c] = n;
        }
        __syncthreads();
        for (int c = 0; c < 128; c++) {
            const ulonglong2* cp = (const ulonglong2*)(scb + c * 64);
            ull d0 = 0ull, d1 = 0ull;
            #pragma unroll
            for (int q = 0; q < 16; q++) {
                ulonglong2 pv = cp[q];
                d0 = ffma2(z2[2 * q], pv.x, d0);
                d1 = ffma2(z2[2 * q + 1], pv.y, d1);
            }
            float a0, a1, a2, a3;
            upk(d0, a0, a1); upk(d1, a2, a3);
            float dot = (a0 + a1) + (a2 + a3);
            float d2 = zz - 2.f * dot + snorm[c];
            if (d2 < best) { best = d2; bi = ch * 128 + c; }
        }
    }
    const float* cbest = cb + bi * 64;
    float* zqp = g_zq + b * D_ * T3_ + t;
    float sse = 0.f;
    #pragma unroll
    for (int d = 0; d < 64; d++) {
        float cv = __ldg(&cbest[d]);
        float df = z[d] - cv;
        sse += df * df;
        zqp[d * T3_] = cv;
    }
    atomicAdd(&shist[bi], 1);
    int lane = tid & 31, w = tid >> 5;
    #pragma unroll
    for (int off = 16; off; off >>= 1) sse += __shfl_down_sync(0xffffffffu, sse, off);
    if (lane == 0) sred[w] = sse;
    __syncthreads();
    if (tid < 8) {
        float v = sred[tid];
        #pragma unroll
        for (int off = 4; off; off >>= 1) v += __shfl_down_sync(0xffu, v, off);
        if (tid == 0) atomicAdd(&g_vq_sse, (double)v);
    }
    __syncthreads();
    for (int i = tid; i < NC; i += 256)
        if (shist[i]) atomicAdd(&g_hist[b * NC + i], shist[i]);
}

__global__ void k_cond(const float* __restrict__ cb, float* __restrict__ out) {
    int b = blockIdx.x, d = threadIdx.x;
    float sum = 0.f;
    for (int c = 0; c < NC; c++)
        sum += (float)g_hist[b * NC + c] * cb[c * 64 + d];
    out[b * 64 + d] = sum * (1.f / (float)T3_);
}

// decT1: z_q -> r1[16,128,8192], relu. z-split ocs, 8 ocs/warp
__global__ __launch_bounds__(256) void k_dec1(const float* __restrict__ db1) {
    __shared__ float s[64][132];
    int b = blockIdx.y, m0 = blockIdx.x * 128, zz = blockIdx.z;
    const float* xin = g_zq + b * D_ * T3_;
    for (int idx = threadIdx.x; idx < 64 * 130; idx += 256) {
        int ic = idx / 130, j = idx - ic * 130;
        int gg = m0 - 1 + j;
        s[ic][j] = (gg >= 0 && gg < T3_) ? xin[ic * T3_ + gg] : 0.f;
    }
    __syncthreads();
    int lane = threadIdx.x & 31, w = threadIdx.x >> 5;
    int M0 = lane * 4, ocb = zz * 64 + w * 8;
    ull acc[8][4];
    #pragma unroll
    for (int i = 0; i < 8; i++) {
        float bv = db1[ocb + i]; ull p = pk(bv, bv);
        #pragma unroll
        for (int j = 0; j < 4; j++) acc[i][j] = p;
    }
    #pragma unroll 1
    for (int ic = 0; ic < 64; ic++) {
        float4 v = *(const float4*)&s[ic][M0];
        float2 v2 = *(const float2*)&s[ic][M0 + 4];
        ull p0 = pk(v.x, v.y), p1 = pk(v.y, v.z), p2 = pk(v.z, v.w);
        ull p3 = pk(v.w, v2.x), p4 = pk(v2.x, v2.y);
        const ulonglong2* Wp = (const ulonglong2*)(g_d1d + (ic * 128 + ocb) * 2);
        #pragma unroll
        for (int i = 0; i < 8; i++) {
            ulonglong2 W = Wp[i];
            acc[i][0] = ffma2(p1, W.y, ffma2(p0, W.x, acc[i][0]));
            acc[i][1] = ffma2(p2, W.y, ffma2(p1, W.x, acc[i][1]));
            acc[i][2] = ffma2(p3, W.y, ffma2(p2, W.x, acc[i][2]));
            acc[i][3] = ffma2(p4, W.y, ffma2(p3, W.x, acc[i][3]));
        }
    }
    #pragma unroll
    for (int i = 0; i < 8; i++) {
        float r[8];
        #pragma unroll
        for (int j = 0; j < 4; j++) upk(acc[i][j], r[2 * j], r[2 * j + 1]);
        float* op = g_r1 + (b * C2 + ocb + i) * T2_ + 2 * m0 + lane * 8;
        float4 s0 = {fmaxf(r[0],0.f), fmaxf(r[1],0.f), fmaxf(r[2],0.f), fmaxf(r[3],0.f)};
        float4 s1 = {fmaxf(r[4],0.f), fmaxf(r[5],0.f), fmaxf(r[6],0.f), fmaxf(r[7],0.f)};
        *(float4*)op = s0; *(float4*)(op + 4) = s1;
    }
}

// decT2: r1 -> r2[16,64,16384], relu. 8 ocs/warp, 2 ic chunks of 64
__global__ __launch_bounds__(256) void k_dec2(const float* __restrict__ db2) {
    __shared__ float s[64][132];
    int b = blockIdx.y, m0 = blockIdx.x * 128;
    const float* xin = g_r1 + b * C2 * T2_;
    int lane = threadIdx.x & 31, w = threadIdx.x >> 5;
    int M0 = lane * 4, ocb = w * 8;
    ull acc[8][4];
    #pragma unroll
    for (int i = 0; i < 8; i++) {
        float bv = db2[ocb + i]; ull p = pk(bv, bv);
        #pragma unroll
        for (int j = 0; j < 4; j++) acc[i][j] = p;
    }
    #pragma unroll 1
    for (int ch = 0; ch < 2; ch++) {
        __syncthreads();
        for (int idx = threadIdx.x; idx < 64 * 130; idx += 256) {
            int ic = idx / 130, j = idx - ic * 130;
            int gg = m0 - 1 + j;
            s[ic][j] = (gg >= 0 && gg < T2_) ? xin[(ch * 64 + ic) * T2_ + gg] : 0.f;
        }
        __syncthreads();
        #pragma unroll 1
        for (int ic = 0; ic < 64; ic++) {
            int icg = ch * 64 + ic;
            float4 v = *(const float4*)&s[ic][M0];
            float2 v2 = *(const float2*)&s[ic][M0 + 4];
            ull p0 = pk(v.x, v.y), p1 = pk(v.y, v.z), p2 = pk(v.z, v.w);
            ull p3 = pk(v.w, v2.x), p4 = pk(v2.x, v2.y);
            const ulonglong2* Wp = (const ulonglong2*)(g_d2d + (icg * 64 + ocb) * 2);
            #pragma unroll
            for (int i = 0; i < 8; i++) {
                ulonglong2 W = Wp[i];
                acc[i][0] = ffma2(p1, W.y, ffma2(p0, W.x, acc[i][0]));
                acc[i][1] = ffma2(p2, W.y, ffma2(p1, W.x, acc[i][1]));
                acc[i][2] = ffma2(p3, W.y, ffma2(p2, W.x, acc[i][2]));
                acc[i][3] = ffma2(p4, W.y, ffma2(p3, W.x, acc[i][3]));
            }
        }
    }
    #pragma unroll
    for (int i = 0; i < 8; i++) {
        float r[8];
        #pragma unroll
        for (int j = 0; j < 4; j++) upk(acc[i][j], r[2 * j], r[2 * j + 1]);
        float* op = g_r2 + (b * C1 + ocb + i) * T1_ + 2 * m0 + lane * 8;
        float4 s0 = {fmaxf(r[0],0.f), fmaxf(r[1],0.f), fmaxf(r[2],0.f), fmaxf(r[3],0.f)};
        float4 s1 = {fmaxf(r[4],0.f), fmaxf(r[5],0.f), fmaxf(r[6],0.f), fmaxf(r[7],0.f)};
        *(float4*)op = s0; *(float4*)(op + 4) = s1;
    }
}

// decT3 fused with recon-MSE
__global__ __launch_bounds__(256) void k_dec3(const float* __restrict__ db3,
                                              const float* __restrict__ x) {
    __shared__ float s[64][132];
    __shared__ float sred[8];
    int b = blockIdx.y, m0 = blockIdx.x * 128;
    const float* xin = g_r2 + b * C1 * T1_;
    for (int idx = threadIdx.x; idx < 64 * 130; idx += 256) {
        int ic = idx / 130, j = idx - ic * 130;
        int gg = m0 - 1 + j;
        s[ic][j] = (gg >= 0 && gg < T1_) ? xin[ic * T1_ + gg] : 0.f;
    }
    __syncthreads();
    int lane = threadIdx.x & 31, w = threadIdx.x >> 5;
    int M0 = lane * 4, oc = w;
    ull acc[4];
    { float bv = db3[oc]; ull p = pk(bv, bv);
      #pragma unroll
      for (int j = 0; j < 4; j++) acc[j] = p; }
    #pragma unroll 1
    for (int ic = 0; ic < 64; ic++) {
        float4 v = *(const float4*)&s[ic][M0];
        float2 v2 = *(const float2*)&s[ic][M0 + 4];
        ull p0 = pk(v.x, v.y), p1 = pk(v.y, v.z), p2 = pk(v.z, v.w);
        ull p3 = pk(v.w, v2.x), p4 = pk(v2.x, v2.y);
        ulonglong2 W = *(const ulonglong2*)(g_d3d + (ic * 8 + oc) * 2);
        acc[0] = ffma2(p1, W.y, ffma2(p0, W.x, acc[0]));
        acc[1] = ffma2(p2, W.y, ffma2(p1, W.x, acc[1]));
        acc[2] = ffma2(p3, W.y, ffma2(p2, W.x, acc[2]));
        acc[3] = ffma2(p4, W.y, ffma2(p3, W.x, acc[3]));
    }
    float r[8];
    #pragma unroll
    for (int j = 0; j < 4; j++) upk(acc[j], r[2 * j], r[2 * j + 1]);
    const float* xr = x + (b * C0 + oc) * T0_ + 2 * m0 + lane * 8;
    float4 xa = *(const float4*)xr;
    float4 xb = *(const float4*)(xr + 4);
    float d0 = r[0]-xa.x, d1 = r[1]-xa.y, d2 = r[2]-xa.z, d3 = r[3]-xa.w;
    float d4 = r[4]-xb.x, d5 = r[5]-xb.y, d6 = r[6]-xb.z, d7 = r[7]-xb.w;
    float ssq = d0*d0 + d1*d1 + d2*d2 + d3*d3 + d4*d4 + d5*d5 + d6*d6 + d7*d7;
    #pragma unroll
    for (int off = 16; off; off >>= 1) ssq += __shfl_down_sync(0xffffffffu, ssq, off);
    if (lane == 0) sred[w] = ssq;
    __syncthreads();
    if (threadIdx.x < 8) {
        float v = sred[threadIdx.x];
        #pragma unroll
        for (int off = 4; off; off >>= 1) v += __shfl_down_sync(0xffu, v, off);
        if (threadIdx.x == 0) atomicAdd(&g_rec_sse, (double)v);
    }
}

__global__ void k_fin(float* __restrict__ out, int out_size) {
    if (out_size >= 1027) {
        float vq = (float)(g_vq_sse / (double)(B_ * D_ * T3_));
        out[1024] = vq;
        out[1025] = vq;
        out[1026] = (float)(g_rec_sse / (double)(B_ * C0 * T0_));
    }
}

extern "C" void kernel_launch(void* const* d_in, const int* in_sizes, int n_in,
                              void* d_out, int out_size) {
    const float* x   = (const float*)d_in[0];
    const float* w1  = (const float*)d_in[1];
    const float* b1  = (const float*)d_in[2];
    const float* w2  = (const float*)d_in[3];
    const float* b2  = (const float*)d_in[4];
    const float* w3  = (const float*)d_in[5];
    const float* b3  = (const float*)d_in[6];
    const float* cb  = (const float*)d_in[7];
    const float* dw1 = (const float*)d_in[8];
    const float* db1 = (const float*)d_in[9];
    const float* dw2 = (const float*)d_in[10];
    const float* db2 = (const float*)d_in[11];
    const float* dw3 = (const float*)d_in[12];
    const float* db3 = (const float*)d_in[13];
    float* out = (float*)d_out;

    k_init<<<32, 256>>>();
    k_prep<<<160, 256>>>(w1, w2, w3, dw1, dw2, dw3);
    k_conv1<<<dim3(T1_ / 128, B_), 256>>>(x, b1);
    k_conv2<<<dim3(T2_ / 128, B_, 2), 256>>>(b2);
    k_conv3<<<dim3(T3_ / 128, B_), 256>>>(b3);
    k_quant<<<(B_ * T3_) / 256, 256>>>(cb);
    k_cond<<<B_, 64>>>(cb, out);
    k_dec1<<<dim3(T3_ / 128, B_, 2), 256>>>(db1);
    k_dec2<<<dim3(T2_ / 128, B_), 256>>>(db2);
    k_dec3<<<dim3(T1_ / 128, B_), 256>>>(db3, x);
    k_fin<<<1, 1>>>(out, out_size);
}